// round 1
// baseline (speedup 1.0000x reference)
#include <cuda_runtime.h>
#include <cstddef>

#define NN    100000
#define NR    7
#define NE    1600000
#define NROWS (NR*NN)          // 700000
#define TOTE  (NR*NE)          // 11200000
#define SCAN_NB ((NROWS + 1023)/1024)   // 684
#define EPS   1e-5f

// ------------------------- scratch (static device memory) -------------------------
__device__ int   g_deg[NROWS];
__device__ int   g_ptr[NROWS];
__device__ int   g_cur[NROWS];
__device__ int   g_bs[SCAN_NB];
__device__ int   g_ssrc[TOTE];
__device__ float g_A1[(size_t)NN*1024];   // [X | mean_0..mean_6]  (layer1 GEMM A)
__device__ float g_A2[(size_t)NN*2048];   // [h1 | mean_0..mean_6] (layer2 GEMM A)
__device__ float g_ACC[(size_t)NN*256];   // GEMM output (reused layer1/layer2)
__device__ float g_H2[(size_t)NN*256];    // layer2 LN output
__device__ float g_Z[(size_t)NN*128];     // classifier hidden
__device__ float g_W1[1024*256];          // concat weights layer1
__device__ float g_W2[2048*256];          // concat weights layer2
__device__ float g_b1s[256];
__device__ float g_b2s[256];

// ------------------------- helpers -------------------------
__device__ __forceinline__ float wred(float s){
    #pragma unroll
    for (int o = 16; o; o >>= 1) s += __shfl_xor_sync(0xffffffffu, s, o);
    return s;
}

// ------------------------- CSR build -------------------------
__global__ void k_zero_deg(){
    int i = blockIdx.x*blockDim.x + threadIdx.x;
    if (i < NROWS) g_deg[i] = 0;
}

__global__ void k_hist(const int* __restrict__ edges){
    int i = blockIdx.x*blockDim.x + threadIdx.x;
    if (i >= TOTE) return;
    int r = i / NE, e = i - r*NE;
    int dst = edges[(size_t)r*2*NE + NE + e];
    atomicAdd(&g_deg[r*NN + dst], 1);
}

// block-level exclusive scan: 256 threads x 4 items
__global__ void k_scan1(){
    __shared__ int sh[256];
    int t = threadIdx.x;
    int base = blockIdx.x*1024 + t*4;
    int v[4];
    #pragma unroll
    for (int i = 0; i < 4; i++){
        int idx = base + i;
        v[i] = (idx < NROWS) ? g_deg[idx] : 0;
    }
    int tsum = v[0]+v[1]+v[2]+v[3];
    sh[t] = tsum; __syncthreads();
    for (int off = 1; off < 256; off <<= 1){
        int x = sh[t];
        int y = (t >= off) ? sh[t-off] : 0;
        __syncthreads();
        sh[t] = x + y;
        __syncthreads();
    }
    int excl = sh[t] - tsum;
    if (t == 255) g_bs[blockIdx.x] = sh[255];
    int run = excl;
    #pragma unroll
    for (int i = 0; i < 4; i++){
        int idx = base + i;
        if (idx < NROWS) g_ptr[idx] = run;
        run += v[i];
    }
}

__global__ void k_scan2(){
    __shared__ int sh[1024];
    int t = threadIdx.x;
    int v = (t < SCAN_NB) ? g_bs[t] : 0;
    sh[t] = v; __syncthreads();
    for (int off = 1; off < 1024; off <<= 1){
        int x = sh[t];
        int y = (t >= off) ? sh[t-off] : 0;
        __syncthreads();
        sh[t] = x + y;
        __syncthreads();
    }
    if (t < SCAN_NB) g_bs[t] = sh[t] - v;   // exclusive
}

__global__ void k_scan3(){
    int i = blockIdx.x*blockDim.x + threadIdx.x;
    if (i >= NROWS) return;
    int val = g_ptr[i] + g_bs[i >> 10];
    g_ptr[i] = val;
    g_cur[i] = val;
}

__global__ void k_fill(const int* __restrict__ edges){
    int i = blockIdx.x*blockDim.x + threadIdx.x;
    if (i >= TOTE) return;
    int r = i / NE, e = i - r*NE;
    int src = edges[(size_t)r*2*NE + e];
    int dst = edges[(size_t)r*2*NE + NE + e];
    int pos = atomicAdd(&g_cur[r*NN + dst], 1);
    g_ssrc[pos] = src;
}

// ------------------------- feature staging -------------------------
__global__ void k_copyX(const float* __restrict__ X){
    size_t i = (size_t)blockIdx.x*blockDim.x + threadIdx.x;
    if (i >= (size_t)NN*128) return;
    size_t v = i >> 7, c = i & 127;
    g_A1[v*1024 + c] = X[i];
}

// one warp per (relation,node) row: register gather-sum, write mean
template<int PER>
__global__ void k_mean(const float* __restrict__ X, int ldx4,
                       float* __restrict__ A, int lda, int coff){
    int gw = (blockIdx.x*blockDim.x + threadIdx.x) >> 5;
    if (gw >= NROWS) return;
    int lane = threadIdx.x & 31;
    int r = gw / NN, v = gw - r*NN;
    int beg = g_ptr[gw], cnt = g_deg[gw];
    float4 s[PER];
    #pragma unroll
    for (int p = 0; p < PER; p++) s[p] = make_float4(0.f,0.f,0.f,0.f);
    const float4* Xb = (const float4*)X;
    for (int e = 0; e < cnt; e++){
        int src = __ldg(&g_ssrc[beg + e]);
        const float4* xr = Xb + (size_t)src*ldx4;
        #pragma unroll
        for (int p = 0; p < PER; p++){
            float4 t = __ldg(&xr[lane + 32*p]);
            s[p].x += t.x; s[p].y += t.y; s[p].z += t.z; s[p].w += t.w;
        }
    }
    float inv = 1.f / fmaxf((float)cnt, 1.f);
    float4* dst = (float4*)(A + (size_t)v*lda + (size_t)coff*(1 + r));
    #pragma unroll
    for (int p = 0; p < PER; p++)
        dst[lane + 32*p] = make_float4(s[p].x*inv, s[p].y*inv, s[p].z*inv, s[p].w*inv);
}

// ------------------------- weight prep -------------------------
__global__ void k_w1(const float* __restrict__ Ws, const float* __restrict__ Wn){
    int i = blockIdx.x*blockDim.x + threadIdx.x;
    if (i >= 1024*256) return;
    int k = i >> 8, n = i & 255;
    float val;
    if (k < 128){
        val = 0.f;
        #pragma unroll
        for (int r = 0; r < NR; r++) val += Ws[((size_t)r*128 + k)*256 + n];
    } else {
        int r = (k >> 7) - 1, kk = k & 127;
        val = Wn[((size_t)r*128 + kk)*256 + n];
    }
    g_W1[i] = val;
}

__global__ void k_w2(const float* __restrict__ Ws, const float* __restrict__ Wn){
    int i = blockIdx.x*blockDim.x + threadIdx.x;
    if (i >= 2048*256) return;
    int k = i >> 8, n = i & 255;
    float val;
    if (k < 256){
        val = 0.f;
        #pragma unroll
        for (int r = 0; r < NR; r++) val += Ws[((size_t)r*256 + k)*256 + n];
    } else {
        int r = (k >> 8) - 1, kk = k & 255;
        val = Wn[((size_t)r*256 + kk)*256 + n];
    }
    g_W2[i] = val;
}

__global__ void k_bsum(const float* __restrict__ b1, const float* __restrict__ b2){
    int c = threadIdx.x;  // 256
    float s1 = 0.f, s2 = 0.f;
    #pragma unroll
    for (int r = 0; r < NR; r++){ s1 += b1[r*256 + c]; s2 += b2[r*256 + c]; }
    g_b1s[c] = s1 * (1.f/7.f);
    g_b2s[c] = s2 * (1.f/7.f);
}

// ------------------------- SGEMM (fp32, 128x128x16 tiles, 8x8 per thread) -------------------------
__global__ void __launch_bounds__(256) k_sgemm(const float* __restrict__ A,
                                               const float* __restrict__ B,
                                               float* __restrict__ C,
                                               int M, int K, int N){
    const int BM = 128, BN = 128, BK = 16;
    __shared__ float As[BK][BM];
    __shared__ float Bs[BK][BN];
    int tid = threadIdx.x;
    int tx = tid & 15, ty = tid >> 4;
    int rowBase = blockIdx.x * BM;
    int colBase = blockIdx.y * BN;
    float acc[8][8] = {};
    float ra[8], rb[8];

    for (int k0 = 0; k0 < K; k0 += BK){
        #pragma unroll
        for (int i = 0; i < 2; i++){
            int fi = tid*2 + i;           // 512 float4 in A tile
            int ar = fi >> 2, ac4 = fi & 3;
            int grow = rowBase + ar;
            float4 v = (grow < M) ? *(const float4*)(A + (size_t)grow*K + k0 + ac4*4)
                                  : make_float4(0.f,0.f,0.f,0.f);
            As[ac4*4+0][ar] = v.x; As[ac4*4+1][ar] = v.y;
            As[ac4*4+2][ar] = v.z; As[ac4*4+3][ar] = v.w;
        }
        #pragma unroll
        for (int i = 0; i < 2; i++){
            int fi = tid*2 + i;           // 512 float4 in B tile
            int br = fi >> 5, bc4 = fi & 31;
            float4 v = *(const float4*)(B + (size_t)(k0+br)*N + colBase + bc4*4);
            *(float4*)&Bs[br][bc4*4] = v;
        }
        __syncthreads();
        #pragma unroll
        for (int kk = 0; kk < BK; kk++){
            #pragma unroll
            for (int i = 0; i < 8; i++) ra[i] = As[kk][ty*8 + i];
            #pragma unroll
            for (int j = 0; j < 8; j++) rb[j] = Bs[kk][tx*8 + j];
            #pragma unroll
            for (int i = 0; i < 8; i++)
                #pragma unroll
                for (int j = 0; j < 8; j++)
                    acc[i][j] += ra[i] * rb[j];
        }
        __syncthreads();
    }
    #pragma unroll
    for (int i = 0; i < 8; i++){
        int grow = rowBase + ty*8 + i;
        if (grow < M){
            float4* cp = (float4*)(C + (size_t)grow*N + colBase + tx*8);
            cp[0] = make_float4(acc[i][0], acc[i][1], acc[i][2], acc[i][3]);
            cp[1] = make_float4(acc[i][4], acc[i][5], acc[i][6], acc[i][7]);
        }
    }
}

// ------------------------- LayerNorm + ReLU (warp per row) -------------------------
__global__ void k_ln(const float* __restrict__ ACC, const float* __restrict__ bsum,
                     const float* __restrict__ g, const float* __restrict__ b,
                     float* __restrict__ out, int ldo){
    int w = (blockIdx.x*blockDim.x + threadIdx.x) >> 5;
    if (w >= NN) return;
    int lane = threadIdx.x & 31;
    float y[8];
    float s = 0.f;
    #pragma unroll
    for (int i = 0; i < 8; i++){
        int c = lane + 32*i;
        y[i] = ACC[(size_t)w*256 + c] * (1.f/7.f) + bsum[c];
        s += y[i];
    }
    float mu = wred(s) * (1.f/256.f);
    float vs = 0.f;
    #pragma unroll
    for (int i = 0; i < 8; i++){ float d = y[i]-mu; vs += d*d; }
    float var = wred(vs) * (1.f/256.f);
    float rs = rsqrtf(var + EPS);
    #pragma unroll
    for (int i = 0; i < 8; i++){
        int c = lane + 32*i;
        out[(size_t)w*ldo + c] = fmaxf(0.f, (y[i]-mu)*rs*g[c] + b[c]);
    }
}

// ------------------------- classifier tail (warp per row) -------------------------
__global__ void k_cls(const float* __restrict__ Zin, const float* __restrict__ bc1,
                      const float* __restrict__ bng, const float* __restrict__ bnb,
                      const float* __restrict__ Wc2, const float* __restrict__ bc2,
                      float* __restrict__ out){
    int w = (blockIdx.x*blockDim.x + threadIdx.x) >> 5;
    if (w >= NN) return;
    int lane = threadIdx.x & 31;
    const float rs = rsqrtf(1.f + EPS);
    float o0 = 0.f, o1 = 0.f;
    #pragma unroll
    for (int i = 0; i < 4; i++){
        int c = lane + 32*i;
        float z = Zin[(size_t)w*128 + c] + bc1[c];
        z = fmaxf(z, 0.f);
        z = z * bng[c] * rs + bnb[c];
        o0 += z * Wc2[c*2 + 0];
        o1 += z * Wc2[c*2 + 1];
    }
    o0 = wred(o0); o1 = wred(o1);
    if (lane == 0){
        out[(size_t)w*2 + 0] = o0 + bc2[0];
        out[(size_t)w*2 + 1] = o1 + bc2[1];
    }
}

// ------------------------- launch -------------------------
template<typename T> static float* symaddr(T& sym){
    void* p = nullptr;
    cudaGetSymbolAddress(&p, sym);
    return (float*)p;
}

extern "C" void kernel_launch(void* const* d_in, const int* in_sizes, int n_in,
                              void* d_out, int out_size){
    const float* features = (const float*)d_in[0];
    const int*   edges    = (const int*)  d_in[1];
    const float* Wself1   = (const float*)d_in[2];
    const float* Wneigh1  = (const float*)d_in[3];
    const float* b1       = (const float*)d_in[4];
    const float* Wself2   = (const float*)d_in[5];
    const float* Wneigh2  = (const float*)d_in[6];
    const float* b2       = (const float*)d_in[7];
    const float* ln_g     = (const float*)d_in[8];
    const float* ln_b     = (const float*)d_in[9];
    const float* Wc1      = (const float*)d_in[10];
    const float* bc1      = (const float*)d_in[11];
    const float* bn_g     = (const float*)d_in[12];
    const float* bn_b     = (const float*)d_in[13];
    const float* Wc2      = (const float*)d_in[14];
    const float* bc2      = (const float*)d_in[15];
    float* out = (float*)d_out;

    float* pA1  = symaddr(g_A1);
    float* pA2  = symaddr(g_A2);
    float* pACC = symaddr(g_ACC);
    float* pH2  = symaddr(g_H2);
    float* pZ   = symaddr(g_Z);
    float* pW1  = symaddr(g_W1);
    float* pW2  = symaddr(g_W2);
    float* pB1s = symaddr(g_b1s);
    float* pB2s = symaddr(g_b2s);

    // --- CSR build (shared by both layers) ---
    k_zero_deg<<<(NROWS+255)/256, 256>>>();
    k_hist<<<(TOTE+255)/256, 256>>>(edges);
    k_scan1<<<SCAN_NB, 256>>>();
    k_scan2<<<1, 1024>>>();
    k_scan3<<<(NROWS+255)/256, 256>>>();
    k_fill<<<(TOTE+255)/256, 256>>>(edges);

    // --- weight prep ---
    k_w1<<<(1024*256)/256, 256>>>(Wself1, Wneigh1);
    k_w2<<<(2048*256)/256, 256>>>(Wself2, Wneigh2);
    k_bsum<<<1, 256>>>(b1, b2);

    // --- layer 1 ---
    k_copyX<<<((size_t)NN*128 + 255)/256, 256>>>(features);
    k_mean<1><<<(NROWS*32 + 255)/256, 256>>>(features, 128/4, pA1, 1024, 128);
    {
        dim3 grid((NN + 127)/128, 2);
        k_sgemm<<<grid, 256>>>(pA1, pW1, pACC, NN, 1024, 256);
    }
    k_ln<<<(NN*32 + 255)/256, 256>>>(pACC, pB1s, ln_g, ln_b, pA2, 2048);

    // --- layer 2 ---
    k_mean<2><<<(NROWS*32 + 255)/256, 256>>>(pA2, 2048/4, pA2, 2048, 256);
    {
        dim3 grid((NN + 127)/128, 2);
        k_sgemm<<<grid, 256>>>(pA2, pW2, pACC, NN, 2048, 256);
    }
    k_ln<<<(NN*32 + 255)/256, 256>>>(pACC, pB2s, ln_g + 256, ln_b + 256, pH2, 256);

    // --- classifier ---
    {
        dim3 grid((NN + 127)/128, 1);
        k_sgemm<<<grid, 256>>>(pH2, Wc1, pZ, NN, 256, 128);
    }
    k_cls<<<(NN*32 + 255)/256, 256>>>(pZ, bc1, bn_g, bn_b, Wc2, bc2, out);
}

// round 3
// speedup vs baseline: 2.1112x; 2.1112x over previous
#include <cuda_runtime.h>
#include <cstdint>
#include <cstddef>

#define NN    100000
#define NR    7
#define NE    1600000
#define NROWS (NR*NN)
#define TOTE  (NR*NE)
#define SCAN_NB ((NROWS + 1023)/1024)
#define EPS   1e-5f

// ------------------------- scratch (static device memory) -------------------------
__device__ int   g_deg[NROWS];
__device__ int   g_ptr[NROWS];
__device__ int   g_cur[NROWS];
__device__ int   g_bs[SCAN_NB];
__device__ int   g_ssrc[TOTE];
__device__ __align__(128) float g_A1[(size_t)(NN+128)*1024];   // [X | mean_0..6], tf32-rounded
__device__ __align__(128) float g_A2[(size_t)(NN+128)*2048];   // [h1 | mean_0..6]
__device__ __align__(128) float g_ACC[(size_t)NN*256];
__device__ __align__(128) float g_H2[(size_t)(NN+128)*256];
__device__ __align__(128) float g_Z[(size_t)NN*128];
__device__ __align__(128) float g_W1[1024*256];                // [K][N], tf32-rounded
__device__ __align__(128) float g_W2[2048*256];
__device__ __align__(128) float g_Wc[256*128];
__device__ float g_b1s[256];
__device__ float g_b2s[256];

// ------------------------- helpers -------------------------
__device__ __forceinline__ float tf32r(float x){
    asm("cvt.rna.tf32.f32 %0, %0;" : "+f"(x));
    return x;
}
__device__ __forceinline__ float wred(float s){
    #pragma unroll
    for (int o = 16; o; o >>= 1) s += __shfl_xor_sync(0xffffffffu, s, o);
    return s;
}
__device__ __forceinline__ uint32_t smem_u32(const void* p){
    uint32_t a;
    asm("{ .reg .u64 t; cvta.to.shared.u64 t, %1; cvt.u32.u64 %0, t; }" : "=r"(a) : "l"(p));
    return a;
}
#define CP_ASYNC16(dst, src) \
    asm volatile("cp.async.cg.shared.global [%0], [%1], 16;" :: "r"(dst), "l"(src))
#define CP_COMMIT() asm volatile("cp.async.commit_group;" ::: "memory")
#define CP_WAIT1()  asm volatile("cp.async.wait_group 1;" ::: "memory")
#define CP_WAIT0()  asm volatile("cp.async.wait_group 0;" ::: "memory")

__device__ __forceinline__ void mma168(float* c, const uint32_t* a, const uint32_t* b){
    asm volatile(
        "mma.sync.aligned.m16n8k8.row.col.f32.tf32.tf32.f32 "
        "{%0,%1,%2,%3}, {%4,%5,%6,%7}, {%8,%9}, {%0,%1,%2,%3};"
        : "+f"(c[0]), "+f"(c[1]), "+f"(c[2]), "+f"(c[3])
        : "r"(a[0]), "r"(a[1]), "r"(a[2]), "r"(a[3]), "r"(b[0]), "r"(b[1]));
}

// ------------------------- CSR build -------------------------
__global__ void k_zero_deg(){
    int i = blockIdx.x*blockDim.x + threadIdx.x;
    if (i < NROWS) g_deg[i] = 0;
}
__global__ void k_hist(const int* __restrict__ edges){
    int i = blockIdx.x*blockDim.x + threadIdx.x;
    if (i >= TOTE) return;
    int r = i / NE, e = i - r*NE;
    int dst = edges[(size_t)r*2*NE + NE + e];
    atomicAdd(&g_deg[r*NN + dst], 1);
}
__global__ void k_scan1(){
    __shared__ int sh[256];
    int t = threadIdx.x;
    int base = blockIdx.x*1024 + t*4;
    int v[4];
    #pragma unroll
    for (int i = 0; i < 4; i++){
        int idx = base + i;
        v[i] = (idx < NROWS) ? g_deg[idx] : 0;
    }
    int tsum = v[0]+v[1]+v[2]+v[3];
    sh[t] = tsum; __syncthreads();
    for (int off = 1; off < 256; off <<= 1){
        int x = sh[t];
        int y = (t >= off) ? sh[t-off] : 0;
        __syncthreads();
        sh[t] = x + y;
        __syncthreads();
    }
    int excl = sh[t] - tsum;
    if (t == 255) g_bs[blockIdx.x] = sh[255];
    int run = excl;
    #pragma unroll
    for (int i = 0; i < 4; i++){
        int idx = base + i;
        if (idx < NROWS) g_ptr[idx] = run;
        run += v[i];
    }
}
__global__ void k_scan2(){
    __shared__ int sh[1024];
    int t = threadIdx.x;
    int v = (t < SCAN_NB) ? g_bs[t] : 0;
    sh[t] = v; __syncthreads();
    for (int off = 1; off < 1024; off <<= 1){
        int x = sh[t];
        int y = (t >= off) ? sh[t-off] : 0;
        __syncthreads();
        sh[t] = x + y;
        __syncthreads();
    }
    if (t < SCAN_NB) g_bs[t] = sh[t] - v;
}
__global__ void k_scan3(){
    int i = blockIdx.x*blockDim.x + threadIdx.x;
    if (i >= NROWS) return;
    int val = g_ptr[i] + g_bs[i >> 10];
    g_ptr[i] = val;
    g_cur[i] = val;
}
__global__ void k_fill(const int* __restrict__ edges){
    int i = blockIdx.x*blockDim.x + threadIdx.x;
    if (i >= TOTE) return;
    int r = i / NE, e = i - r*NE;
    int src = edges[(size_t)r*2*NE + e];
    int dst = edges[(size_t)r*2*NE + NE + e];
    int pos = atomicAdd(&g_cur[r*NN + dst], 1);
    g_ssrc[pos] = src;
}

// ------------------------- feature staging -------------------------
__global__ void k_copyX(const float* __restrict__ X){
    size_t i = (size_t)blockIdx.x*blockDim.x + threadIdx.x;
    if (i >= (size_t)NN*128) return;
    size_t v = i >> 7, c = i & 127;
    g_A1[v*1024 + c] = tf32r(X[i]);
}

// one warp per (relation,node) row: register gather-sum, write tf32-rounded mean
template<int PER>
__global__ void k_mean(const float* __restrict__ X, int ldx4,
                       float* __restrict__ A, int lda, int coff){
    int gw = (blockIdx.x*blockDim.x + threadIdx.x) >> 5;
    if (gw >= NROWS) return;
    int lane = threadIdx.x & 31;
    int r = gw / NN, v = gw - r*NN;
    int beg = g_ptr[gw], cnt = g_deg[gw];
    float4 s[PER];
    #pragma unroll
    for (int p = 0; p < PER; p++) s[p] = make_float4(0.f,0.f,0.f,0.f);
    const float4* Xb = (const float4*)X;
    for (int e = 0; e < cnt; e++){
        int src = __ldg(&g_ssrc[beg + e]);
        const float4* xr = Xb + (size_t)src*ldx4;
        #pragma unroll
        for (int p = 0; p < PER; p++){
            float4 t = __ldg(&xr[lane + 32*p]);
            s[p].x += t.x; s[p].y += t.y; s[p].z += t.z; s[p].w += t.w;
        }
    }
    float inv = 1.f / fmaxf((float)cnt, 1.f);
    float4* dst = (float4*)(A + (size_t)v*lda + (size_t)coff*(1 + r));
    #pragma unroll
    for (int p = 0; p < PER; p++)
        dst[lane + 32*p] = make_float4(tf32r(s[p].x*inv), tf32r(s[p].y*inv),
                                       tf32r(s[p].z*inv), tf32r(s[p].w*inv));
}

// ------------------------- weight prep ([K][N], tf32 rounded) -------------------------
__global__ void k_w1(const float* __restrict__ Ws, const float* __restrict__ Wn){
    int i = blockIdx.x*blockDim.x + threadIdx.x;
    if (i >= 1024*256) return;
    int k = i >> 8, n = i & 255;
    float val;
    if (k < 128){
        val = 0.f;
        #pragma unroll
        for (int r = 0; r < NR; r++) val += Ws[((size_t)r*128 + k)*256 + n];
    } else {
        int r = (k >> 7) - 1, kk = k & 127;
        val = Wn[((size_t)r*128 + kk)*256 + n];
    }
    g_W1[i] = tf32r(val);
}
__global__ void k_w2(const float* __restrict__ Ws, const float* __restrict__ Wn){
    int i = blockIdx.x*blockDim.x + threadIdx.x;
    if (i >= 2048*256) return;
    int k = i >> 8, n = i & 255;
    float val;
    if (k < 256){
        val = 0.f;
        #pragma unroll
        for (int r = 0; r < NR; r++) val += Ws[((size_t)r*256 + k)*256 + n];
    } else {
        int r = (k >> 8) - 1, kk = k & 255;
        val = Wn[((size_t)r*256 + kk)*256 + n];
    }
    g_W2[i] = tf32r(val);
}
__global__ void k_wc(const float* __restrict__ Wc1){
    int i = blockIdx.x*blockDim.x + threadIdx.x;
    if (i >= 256*128) return;
    g_Wc[i] = tf32r(Wc1[i]);
}
__global__ void k_bsum(const float* __restrict__ b1, const float* __restrict__ b2){
    int c = threadIdx.x;
    float s1 = 0.f, s2 = 0.f;
    #pragma unroll
    for (int r = 0; r < NR; r++){ s1 += b1[r*256 + c]; s2 += b2[r*256 + c]; }
    g_b1s[c] = s1 * (1.f/7.f);
    g_b2s[c] = s2 * (1.f/7.f);
}

// ------------------------- tf32 tensor-core GEMM -------------------------
// C[M,N] = A[M,K] @ B[K,N]. Block 128x128x32, 8 warps (2m x 4n), warp 64x32,
// mma.m16n8k8.tf32, cp.async.cg double-buffered SMEM.
// SMEM strides: A rows padded to 36 floats, B rows padded to 136 floats
// (fragment LDS provably conflict-free).
#define AS_STRIDE 36
#define BS_STRIDE 136
#define ASZ (128*AS_STRIDE)          // floats
#define BSZ (32*BS_STRIDE)
#define GEMM_SMEM ((2*ASZ + 2*BSZ)*4)

__global__ void __launch_bounds__(256, 2) k_mma(
    const float* __restrict__ A, int lda,
    const float* __restrict__ B, int ldb,
    float* __restrict__ C, int ldc,
    int K, int M)
{
    extern __shared__ float sm[];
    float* Abuf[2] = { sm, sm + ASZ };
    float* Bbuf[2] = { sm + 2*ASZ, sm + 2*ASZ + BSZ };

    int tid = threadIdx.x, wid = tid >> 5, lane = tid & 31;
    int warpRow = (wid >> 2) * 64;
    int warpCol = (wid & 3) * 32;
    int rowBase = blockIdx.x * 128;
    int colBase = blockIdx.y * 128;

    // precomputed cp.async indices
    int ar = tid >> 3, ac4 = (tid & 7) * 4;        // A: 4 iterations stride 32 rows
    int br = tid >> 5, bn4 = (tid & 31) * 4;       // B: iterations stride 8 rows

    uint32_t sA[2], sB[2];
    sA[0] = smem_u32(Abuf[0]); sA[1] = smem_u32(Abuf[1]);
    sB[0] = smem_u32(Bbuf[0]); sB[1] = smem_u32(Bbuf[1]);

    float acc[4][4][4] = {};

    const int nT = K >> 5;

    // ---- tile loader ----
    auto load_tile = [&](int t, int buf){
        int k0 = t << 5;
        #pragma unroll
        for (int i = 0; i < 4; i++){
            int r = ar + i*32;
            const float* src = A + (size_t)(rowBase + r)*lda + k0 + ac4;
            CP_ASYNC16(sA[buf] + (r*AS_STRIDE + ac4)*4, src);
        }
        #pragma unroll
        for (int i = 0; i < 4; i++){
            int r = br + i*8;
            const float* src = B + (size_t)(k0 + r)*ldb + colBase + bn4;
            CP_ASYNC16(sB[buf] + (r*BS_STRIDE + bn4)*4, src);
        }
        CP_COMMIT();
    };

    load_tile(0, 0);

    for (int t = 0; t < nT; t++){
        int buf = t & 1;
        if (t + 1 < nT){ load_tile(t+1, buf^1); CP_WAIT1(); }
        else           { CP_WAIT0(); }
        __syncthreads();

        const float* As = Abuf[buf];
        const float* Bs = Bbuf[buf];
        #pragma unroll
        for (int kk = 0; kk < 4; kk++){
            uint32_t a[4][4], b[4][2];
            int arow = warpRow + (lane >> 2);
            int acol = kk*8 + (lane & 3);
            #pragma unroll
            for (int mt = 0; mt < 4; mt++){
                const float* ap = As + (arow + mt*16)*AS_STRIDE + acol;
                a[mt][0] = __float_as_uint(ap[0]);
                a[mt][1] = __float_as_uint(ap[8*AS_STRIDE]);
                a[mt][2] = __float_as_uint(ap[4]);
                a[mt][3] = __float_as_uint(ap[8*AS_STRIDE + 4]);
            }
            int brow = kk*8 + (lane & 3);
            int bcol = warpCol + (lane >> 2);
            #pragma unroll
            for (int nt = 0; nt < 4; nt++){
                const float* bp = Bs + brow*BS_STRIDE + bcol + nt*8;
                b[nt][0] = __float_as_uint(bp[0]);
                b[nt][1] = __float_as_uint(bp[4*BS_STRIDE]);
            }
            #pragma unroll
            for (int mt = 0; mt < 4; mt++)
                #pragma unroll
                for (int nt = 0; nt < 4; nt++)
                    mma168(acc[mt][nt], a[mt], b[nt]);
        }
        __syncthreads();
    }

    // epilogue: float2 stores, row-guarded
    #pragma unroll
    for (int mt = 0; mt < 4; mt++){
        int r0 = rowBase + warpRow + mt*16 + (lane >> 2);
        int r1 = r0 + 8;
        #pragma unroll
        for (int nt = 0; nt < 4; nt++){
            int c0 = colBase + warpCol + nt*8 + (lane & 3)*2;
            if (r0 < M) *(float2*)(C + (size_t)r0*ldc + c0) = make_float2(acc[mt][nt][0], acc[mt][nt][1]);
            if (r1 < M) *(float2*)(C + (size_t)r1*ldc + c0) = make_float2(acc[mt][nt][2], acc[mt][nt][3]);
        }
    }
}

// ------------------------- LayerNorm + ReLU (warp per row, tf32-rounded out) ---------
__global__ void k_ln(const float* __restrict__ ACC, const float* __restrict__ bsum,
                     const float* __restrict__ g, const float* __restrict__ b,
                     float* __restrict__ out, int ldo){
    int w = (blockIdx.x*blockDim.x + threadIdx.x) >> 5;
    if (w >= NN) return;
    int lane = threadIdx.x & 31;
    float y[8];
    float s = 0.f;
    #pragma unroll
    for (int i = 0; i < 8; i++){
        int c = lane + 32*i;
        y[i] = ACC[(size_t)w*256 + c] * (1.f/7.f) + bsum[c];
        s += y[i];
    }
    float mu = wred(s) * (1.f/256.f);
    float vs = 0.f;
    #pragma unroll
    for (int i = 0; i < 8; i++){ float d = y[i]-mu; vs += d*d; }
    float var = wred(vs) * (1.f/256.f);
    float rs = rsqrtf(var + EPS);
    #pragma unroll
    for (int i = 0; i < 8; i++){
        int c = lane + 32*i;
        out[(size_t)w*ldo + c] = tf32r(fmaxf(0.f, (y[i]-mu)*rs*g[c] + b[c]));
    }
}

// ------------------------- classifier tail (warp per row) -------------------------
__global__ void k_cls(const float* __restrict__ Zin, const float* __restrict__ bc1,
                      const float* __restrict__ bng, const float* __restrict__ bnb,
                      const float* __restrict__ Wc2, const float* __restrict__ bc2,
                      float* __restrict__ out){
    int w = (blockIdx.x*blockDim.x + threadIdx.x) >> 5;
    if (w >= NN) return;
    int lane = threadIdx.x & 31;
    const float rs = rsqrtf(1.f + EPS);
    float o0 = 0.f, o1 = 0.f;
    #pragma unroll
    for (int i = 0; i < 4; i++){
        int c = lane + 32*i;
        float z = Zin[(size_t)w*128 + c] + bc1[c];
        z = fmaxf(z, 0.f);
        z = z * bng[c] * rs + bnb[c];
        o0 += z * Wc2[c*2 + 0];
        o1 += z * Wc2[c*2 + 1];
    }
    o0 = wred(o0); o1 = wred(o1);
    if (lane == 0){
        out[(size_t)w*2 + 0] = o0 + bc2[0];
        out[(size_t)w*2 + 1] = o1 + bc2[1];
    }
}

// ------------------------- launch -------------------------
template<typename T> static float* symaddr(T& sym){
    void* p = nullptr;
    cudaGetSymbolAddress(&p, sym);
    return (float*)p;
}

extern "C" void kernel_launch(void* const* d_in, const int* in_sizes, int n_in,
                              void* d_out, int out_size){
    const float* features = (const float*)d_in[0];
    const int*   edges    = (const int*)  d_in[1];
    const float* Wself1   = (const float*)d_in[2];
    const float* Wneigh1  = (const float*)d_in[3];
    const float* b1       = (const float*)d_in[4];
    const float* Wself2   = (const float*)d_in[5];
    const float* Wneigh2  = (const float*)d_in[6];
    const float* b2       = (const float*)d_in[7];
    const float* ln_g     = (const float*)d_in[8];
    const float* ln_b     = (const float*)d_in[9];
    const float* Wc1      = (const float*)d_in[10];
    const float* bc1      = (const float*)d_in[11];
    const float* bn_g     = (const float*)d_in[12];
    const float* bn_b     = (const float*)d_in[13];
    const float* Wc2      = (const float*)d_in[14];
    const float* bc2      = (const float*)d_in[15];
    float* out = (float*)d_out;

    float* pA1  = symaddr(g_A1);
    float* pA2  = symaddr(g_A2);
    float* pACC = symaddr(g_ACC);
    float* pH2  = symaddr(g_H2);
    float* pZ   = symaddr(g_Z);
    float* pW1  = symaddr(g_W1);
    float* pW2  = symaddr(g_W2);
    float* pWc  = symaddr(g_Wc);
    float* pB1s = symaddr(g_b1s);
    float* pB2s = symaddr(g_b2s);

    static int smem_set = 0;
    if (!smem_set){
        cudaFuncSetAttribute(k_mma, cudaFuncAttributeMaxDynamicSharedMemorySize, GEMM_SMEM);
        smem_set = 1;
    }

    // --- CSR build ---
    k_zero_deg<<<(NROWS+255)/256, 256>>>();
    k_hist<<<(TOTE+255)/256, 256>>>(edges);
    k_scan1<<<SCAN_NB, 256>>>();
    k_scan2<<<1, 1024>>>();
    k_scan3<<<(NROWS+255)/256, 256>>>();
    k_fill<<<(TOTE+255)/256, 256>>>(edges);

    // --- weight prep ---
    k_w1<<<(1024*256)/256, 256>>>(Wself1, Wneigh1);
    k_w2<<<(2048*256)/256, 256>>>(Wself2, Wneigh2);
    k_wc<<<(256*128)/256, 256>>>(Wc1);
    k_bsum<<<1, 256>>>(b1, b2);

    const int MT = (NN + 127)/128;   // 782

    // --- layer 1 ---
    k_copyX<<<((size_t)NN*128 + 255)/256, 256>>>(features);
    k_mean<1><<<(NROWS*32 + 255)/256, 256>>>(features, 128/4, pA1, 1024, 128);
    k_mma<<<dim3(MT, 2), 256, GEMM_SMEM>>>(pA1, 1024, pW1, 256, pACC, 256, 1024, NN);
    k_ln<<<(NN*32 + 255)/256, 256>>>(pACC, pB1s, ln_g, ln_b, pA2, 2048);

    // --- layer 2 ---
    k_mean<2><<<(NROWS*32 + 255)/256, 256>>>(pA2, 2048/4, pA2, 2048, 256);
    k_mma<<<dim3(MT, 2), 256, GEMM_SMEM>>>(pA2, 2048, pW2, 256, pACC, 256, 2048, NN);
    k_ln<<<(NN*32 + 255)/256, 256>>>(pACC, pB2s, ln_g + 256, ln_b + 256, pH2, 256);

    // --- classifier ---
    k_mma<<<dim3(MT, 1), 256, GEMM_SMEM>>>(pH2, 256, pWc, 128, pZ, 128, 256, NN);
    k_cls<<<(NN*32 + 255)/256, 256>>>(pZ, bc1, bn_g, bn_b, Wc2, bc2, out);
}

// round 5
// speedup vs baseline: 3.3354x; 1.5799x over previous
#include <cuda_runtime.h>
#include <cuda_fp16.h>
#include <cstdint>
#include <cstddef>

#define NN    100000
#define NR    7
#define NE    1600000
#define NROWS (NR*NN)
#define TOTE  (NR*NE)
#define SCAN_NB ((NROWS + 1023)/1024)
#define EPS   1e-5f

// ------------------------- scratch (static device memory) -------------------------
__device__ int   g_deg[NROWS];
__device__ int   g_ptr[NROWS];
__device__ int   g_cur[NROWS];
__device__ int   g_bs[SCAN_NB];
__device__ int   g_ssrc[TOTE];
__device__ __align__(128) __half g_A1[(size_t)(NN+128)*1024];   // [X | mean_0..6] fp16
__device__ __align__(128) __half g_A2[(size_t)(NN+128)*2048];   // [h1 | mean_0..6] fp16
__device__ __align__(128) float  g_ACC[(size_t)NN*256];         // GEMM out fp32
__device__ __align__(128) __half g_H2[(size_t)(NN+128)*256];    // layer2 LN out fp16
__device__ __align__(128) float  g_Z[(size_t)NN*128];           // classifier hidden fp32
__device__ __align__(128) __half g_W1T[256*1024];               // [N][K] fp16
__device__ __align__(128) __half g_W2T[256*2048];
__device__ __align__(128) __half g_WcT[128*256];
__device__ float g_b1s[256];
__device__ float g_b2s[256];

// ------------------------- helpers -------------------------
__device__ __forceinline__ float wred(float s){
    #pragma unroll
    for (int o = 16; o; o >>= 1) s += __shfl_xor_sync(0xffffffffu, s, o);
    return s;
}
__device__ __forceinline__ uint32_t smem_u32(const void* p){
    uint32_t a;
    asm("{ .reg .u64 t; cvta.to.shared.u64 t, %1; cvt.u32.u64 %0, t; }" : "=r"(a) : "l"(p));
    return a;
}
#define CP_ASYNC16(dst, src) \
    asm volatile("cp.async.cg.shared.global [%0], [%1], 16;" :: "r"(dst), "l"(src))
#define CP_COMMIT() asm volatile("cp.async.commit_group;" ::: "memory")
#define CP_WAIT1()  asm volatile("cp.async.wait_group 1;" ::: "memory")
#define CP_WAIT0()  asm volatile("cp.async.wait_group 0;" ::: "memory")

__device__ __forceinline__ void mma16816(float* c, const uint32_t* a, const uint32_t* b){
    asm volatile(
        "mma.sync.aligned.m16n8k16.row.col.f32.f16.f16.f32 "
        "{%0,%1,%2,%3}, {%4,%5,%6,%7}, {%8,%9}, {%0,%1,%2,%3};"
        : "+f"(c[0]), "+f"(c[1]), "+f"(c[2]), "+f"(c[3])
        : "r"(a[0]), "r"(a[1]), "r"(a[2]), "r"(a[3]), "r"(b[0]), "r"(b[1]));
}

// ------------------------- CSR build -------------------------
__global__ void k_zero_deg(){
    int i = blockIdx.x*blockDim.x + threadIdx.x;
    if (i < NROWS) g_deg[i] = 0;
}
__global__ void k_hist(const int* __restrict__ edges){
    int i = blockIdx.x*blockDim.x + threadIdx.x;
    if (i >= TOTE) return;
    int r = i / NE, e = i - r*NE;
    int dst = edges[(size_t)r*2*NE + NE + e];
    atomicAdd(&g_deg[r*NN + dst], 1);
}
__global__ void k_scan1(){
    __shared__ int sh[256];
    int t = threadIdx.x;
    int base = blockIdx.x*1024 + t*4;
    int v[4];
    #pragma unroll
    for (int i = 0; i < 4; i++){
        int idx = base + i;
        v[i] = (idx < NROWS) ? g_deg[idx] : 0;
    }
    int tsum = v[0]+v[1]+v[2]+v[3];
    sh[t] = tsum; __syncthreads();
    for (int off = 1; off < 256; off <<= 1){
        int x = sh[t];
        int y = (t >= off) ? sh[t-off] : 0;
        __syncthreads();
        sh[t] = x + y;
        __syncthreads();
    }
    int excl = sh[t] - tsum;
    if (t == 255) g_bs[blockIdx.x] = sh[255];
    int run = excl;
    #pragma unroll
    for (int i = 0; i < 4; i++){
        int idx = base + i;
        if (idx < NROWS) g_ptr[idx] = run;
        run += v[i];
    }
}
__global__ void k_scan2(){
    __shared__ int sh[1024];
    int t = threadIdx.x;
    int v = (t < SCAN_NB) ? g_bs[t] : 0;
    sh[t] = v; __syncthreads();
    for (int off = 1; off < 1024; off <<= 1){
        int x = sh[t];
        int y = (t >= off) ? sh[t-off] : 0;
        __syncthreads();
        sh[t] = x + y;
        __syncthreads();
    }
    if (t < SCAN_NB) g_bs[t] = sh[t] - v;
}
__global__ void k_scan3(){
    int i = blockIdx.x*blockDim.x + threadIdx.x;
    if (i >= NROWS) return;
    int val = g_ptr[i] + g_bs[i >> 10];
    g_ptr[i] = val;
    g_cur[i] = val;
}
__global__ void k_fill(const int* __restrict__ edges){
    int i = blockIdx.x*blockDim.x + threadIdx.x;
    if (i >= TOTE) return;
    int r = i / NE, e = i - r*NE;
    int src = edges[(size_t)r*2*NE + e];
    int dst = edges[(size_t)r*2*NE + NE + e];
    int pos = atomicAdd(&g_cur[r*NN + dst], 1);
    g_ssrc[pos] = src;
}

// ------------------------- feature staging (fp32 -> fp16 into A1) ---------------
__global__ void k_copyX(const float* __restrict__ X){
    size_t i = (size_t)blockIdx.x*blockDim.x + threadIdx.x;     // float4 units
    if (i >= (size_t)NN*32) return;
    size_t v = i >> 5, c4 = i & 31;
    float4 f = ((const float4*)X)[i];
    __half2 h0 = __floats2half2_rn(f.x, f.y);
    __half2 h1 = __floats2half2_rn(f.z, f.w);
    uint2 o; o.x = *(uint32_t*)&h0; o.y = *(uint32_t*)&h1;
    *((uint2*)(g_A1 + v*1024) + c4) = o;
}

// ------------------------- mean gather (fp16 rows, fp32 accumulate) --------------
// one warp per (relation,node) row. U2 = uint2 (4 halves) per lane. 32*4*U2 cols.
template<int U2>
__global__ void k_mean_h(const __half* __restrict__ X, int ldx,
                         __half* __restrict__ A, int lda, int coff){
    int gw = (blockIdx.x*blockDim.x + threadIdx.x) >> 5;
    if (gw >= NROWS) return;
    int lane = threadIdx.x & 31;
    int r = gw / NN, v = gw - r*NN;
    int beg = g_ptr[gw], cnt = g_deg[gw];
    float2 s[2*U2];
    #pragma unroll
    for (int u = 0; u < 2*U2; u++) s[u] = make_float2(0.f, 0.f);
    const int* sp = g_ssrc + beg;
    int e = 0;
    for (; e + 2 <= cnt; e += 2){
        int s0 = __ldg(sp + e);
        int s1 = __ldg(sp + e + 1);
        const uint2* x0 = (const uint2*)(X + (size_t)s0*ldx) + lane*U2;
        const uint2* x1 = (const uint2*)(X + (size_t)s1*ldx) + lane*U2;
        uint2 t0[U2], t1[U2];
        #pragma unroll
        for (int u = 0; u < U2; u++){ t0[u] = __ldg(&x0[u]); t1[u] = __ldg(&x1[u]); }
        #pragma unroll
        for (int u = 0; u < U2; u++){
            float2 a0 = __half22float2(*(__half2*)&t0[u].x);
            float2 b0 = __half22float2(*(__half2*)&t0[u].y);
            float2 a1 = __half22float2(*(__half2*)&t1[u].x);
            float2 b1 = __half22float2(*(__half2*)&t1[u].y);
            s[2*u].x   += a0.x + a1.x;  s[2*u].y   += a0.y + a1.y;
            s[2*u+1].x += b0.x + b1.x;  s[2*u+1].y += b0.y + b1.y;
        }
    }
    if (e < cnt){
        int s0 = __ldg(sp + e);
        const uint2* x0 = (const uint2*)(X + (size_t)s0*ldx) + lane*U2;
        #pragma unroll
        for (int u = 0; u < U2; u++){
            uint2 t0 = __ldg(&x0[u]);
            float2 a0 = __half22float2(*(__half2*)&t0.x);
            float2 b0 = __half22float2(*(__half2*)&t0.y);
            s[2*u].x += a0.x; s[2*u].y += a0.y;
            s[2*u+1].x += b0.x; s[2*u+1].y += b0.y;
        }
    }
    float inv = 1.f / fmaxf((float)cnt, 1.f);
    uint2* dst = (uint2*)(A + (size_t)v*lda + (size_t)coff*(1 + r)) + lane*U2;
    #pragma unroll
    for (int u = 0; u < U2; u++){
        __half2 h0 = __floats2half2_rn(s[2*u].x*inv,   s[2*u].y*inv);
        __half2 h1 = __floats2half2_rn(s[2*u+1].x*inv, s[2*u+1].y*inv);
        uint2 o; o.x = *(uint32_t*)&h0; o.y = *(uint32_t*)&h1;
        dst[u] = o;
    }
}

// ------------------------- weight prep ([N][K] fp16) -------------------------
__global__ void k_w1(const float* __restrict__ Ws, const float* __restrict__ Wn){
    int i = blockIdx.x*blockDim.x + threadIdx.x;
    if (i >= 256*1024) return;
    int n = i >> 10, k = i & 1023;
    float val;
    if (k < 128){
        val = 0.f;
        #pragma unroll
        for (int r = 0; r < NR; r++) val += Ws[((size_t)r*128 + k)*256 + n];
    } else {
        int r = (k >> 7) - 1, kk = k & 127;
        val = Wn[((size_t)r*128 + kk)*256 + n];
    }
    g_W1T[i] = __float2half(val);
}
__global__ void k_w2(const float* __restrict__ Ws, const float* __restrict__ Wn){
    int i = blockIdx.x*blockDim.x + threadIdx.x;
    if (i >= 256*2048) return;
    int n = i >> 11, k = i & 2047;
    float val;
    if (k < 256){
        val = 0.f;
        #pragma unroll
        for (int r = 0; r < NR; r++) val += Ws[((size_t)r*256 + k)*256 + n];
    } else {
        int r = (k >> 8) - 1, kk = k & 255;
        val = Wn[((size_t)r*256 + kk)*256 + n];
    }
    g_W2T[i] = __float2half(val);
}
__global__ void k_wc(const float* __restrict__ Wc1){
    int i = blockIdx.x*blockDim.x + threadIdx.x;
    if (i >= 128*256) return;
    int n = i >> 8, k = i & 255;
    g_WcT[i] = __float2half(Wc1[(size_t)k*128 + n]);
}
__global__ void k_bsum(const float* __restrict__ b1, const float* __restrict__ b2){
    int c = threadIdx.x;
    float s1 = 0.f, s2 = 0.f;
    #pragma unroll
    for (int r = 0; r < NR; r++){ s1 += b1[r*256 + c]; s2 += b2[r*256 + c]; }
    g_b1s[c] = s1 * (1.f/7.f);
    g_b2s[c] = s2 * (1.f/7.f);
}

// ------------------------- fp16 tensor-core GEMM -------------------------
// C[M,N] = A[M,K] @ BT[N,K]^T. Block 128x128x32, 8 warps (2m x 4n), warp 64x32,
// mma.m16n8k16.f16 (fp32 accum), cp.async double-buffered SMEM.
// SMEM rows padded to 40 halves (80B): fragment .b32 LDS conflict-free.
#define STRH 40
#define TILE_H (128*STRH)               // halves per tile
#define GEMM_SMEM (4*TILE_H*2)          // bytes (A0,A1,B0,B1)

__global__ void __launch_bounds__(256, 2) k_hmma(
    const __half* __restrict__ A, int lda,
    const __half* __restrict__ BT, int ldb,
    float* __restrict__ C, int ldc,
    int K, int M)
{
    extern __shared__ __half sm[];
    __half* Ab[2] = { sm,            sm + TILE_H };
    __half* Bb[2] = { sm + 2*TILE_H, sm + 3*TILE_H };

    int tid = threadIdx.x, wid = tid >> 5, lane = tid & 31;
    int warpRow = (wid >> 2) * 64;
    int warpCol = (wid & 3) * 32;
    int rowBase = blockIdx.x * 128;
    int colBase = blockIdx.y * 128;

    uint32_t sA[2], sB[2];
    sA[0] = smem_u32(Ab[0]); sA[1] = smem_u32(Ab[1]);
    sB[0] = smem_u32(Bb[0]); sB[1] = smem_u32(Bb[1]);

    float acc[4][4][4] = {};
    const int nT = K >> 5;

    auto load_tile = [&](int t, int buf){
        int k0 = t << 5;
        #pragma unroll
        for (int i = 0; i < 2; i++){
            int idx = i*256 + tid;
            int row = idx >> 2, ch = idx & 3;     // 4 x 16B per 64B row
            const __half* srcA = A + (size_t)(rowBase + row)*lda + k0 + ch*8;
            CP_ASYNC16(sA[buf] + (row*STRH + ch*8)*2, srcA);
            const __half* srcB = BT + (size_t)(colBase + row)*ldb + k0 + ch*8;
            CP_ASYNC16(sB[buf] + (row*STRH + ch*8)*2, srcB);
        }
        CP_COMMIT();
    };

    load_tile(0, 0);

    for (int t = 0; t < nT; t++){
        int buf = t & 1;
        if (t + 1 < nT){ load_tile(t+1, buf^1); CP_WAIT1(); }
        else           { CP_WAIT0(); }
        __syncthreads();

        const __half* As = Ab[buf];
        const __half* Bs = Bb[buf];
        #pragma unroll
        for (int kk = 0; kk < 2; kk++){
            uint32_t a[4][4], b[4][2];
            int ar = warpRow + (lane >> 2);
            int c0 = kk*16 + (lane & 3)*2;
            #pragma unroll
            for (int mt = 0; mt < 4; mt++){
                const __half* ap = As + (ar + mt*16)*STRH + c0;
                a[mt][0] = *(const uint32_t*)(ap);
                a[mt][1] = *(const uint32_t*)(ap + 8*STRH);
                a[mt][2] = *(const uint32_t*)(ap + 8);
                a[mt][3] = *(const uint32_t*)(ap + 8*STRH + 8);
            }
            int bn = warpCol + (lane >> 2);
            #pragma unroll
            for (int nt = 0; nt < 4; nt++){
                const __half* bp = Bs + (bn + nt*8)*STRH + c0;
                b[nt][0] = *(const uint32_t*)(bp);
                b[nt][1] = *(const uint32_t*)(bp + 8);
            }
            #pragma unroll
            for (int mt = 0; mt < 4; mt++)
                #pragma unroll
                for (int nt = 0; nt < 4; nt++)
                    mma16816(acc[mt][nt], a[mt], b[nt]);
        }
        __syncthreads();
    }

    #pragma unroll
    for (int mt = 0; mt < 4; mt++){
        int r0 = rowBase + warpRow + mt*16 + (lane >> 2);
        int r1 = r0 + 8;
        #pragma unroll
        for (int nt = 0; nt < 4; nt++){
            int c0 = colBase + warpCol + nt*8 + (lane & 3)*2;
            if (r0 < M) *(float2*)(C + (size_t)r0*ldc + c0) = make_float2(acc[mt][nt][0], acc[mt][nt][1]);
            if (r1 < M) *(float2*)(C + (size_t)r1*ldc + c0) = make_float2(acc[mt][nt][2], acc[mt][nt][3]);
        }
    }
}

// ------------------------- LayerNorm + ReLU (warp per row, fp16 out) -----------
__global__ void k_ln(const float* __restrict__ ACC, const float* __restrict__ bsum,
                     const float* __restrict__ g, const float* __restrict__ b,
                     __half* __restrict__ out, int ldo){
    int w = (blockIdx.x*blockDim.x + threadIdx.x) >> 5;
    if (w >= NN) return;
    int lane = threadIdx.x & 31;
    const float4* ap = (const float4*)(ACC + (size_t)w*256) + lane*2;
    const float4* bp = (const float4*)bsum + lane*2;
    float4 v0 = ap[0], v1 = ap[1];
    float4 s0 = bp[0], s1 = bp[1];
    float y[8];
    y[0] = v0.x*(1.f/7.f) + s0.x; y[1] = v0.y*(1.f/7.f) + s0.y;
    y[2] = v0.z*(1.f/7.f) + s0.z; y[3] = v0.w*(1.f/7.f) + s0.w;
    y[4] = v1.x*(1.f/7.f) + s1.x; y[5] = v1.y*(1.f/7.f) + s1.y;
    y[6] = v1.z*(1.f/7.f) + s1.z; y[7] = v1.w*(1.f/7.f) + s1.w;
    float s = 0.f;
    #pragma unroll
    for (int i = 0; i < 8; i++) s += y[i];
    float mu = wred(s) * (1.f/256.f);
    float vs = 0.f;
    #pragma unroll
    for (int i = 0; i < 8; i++){ float d = y[i]-mu; vs += d*d; }
    float var = wred(vs) * (1.f/256.f);
    float rstd = rsqrtf(var + EPS);
    const float4* gp = (const float4*)g + lane*2;
    const float4* bbp = (const float4*)b + lane*2;
    float4 g0 = gp[0], g1 = gp[1];
    float4 b0 = bbp[0], b1 = bbp[1];
    float go[8] = {g0.x,g0.y,g0.z,g0.w,g1.x,g1.y,g1.z,g1.w};
    float bo[8] = {b0.x,b0.y,b0.z,b0.w,b1.x,b1.y,b1.z,b1.w};
    uint2 o[2];
    #pragma unroll
    for (int h = 0; h < 2; h++){
        float r0 = fmaxf(0.f, (y[h*4+0]-mu)*rstd*go[h*4+0] + bo[h*4+0]);
        float r1 = fmaxf(0.f, (y[h*4+1]-mu)*rstd*go[h*4+1] + bo[h*4+1]);
        float r2 = fmaxf(0.f, (y[h*4+2]-mu)*rstd*go[h*4+2] + bo[h*4+2]);
        float r3 = fmaxf(0.f, (y[h*4+3]-mu)*rstd*go[h*4+3] + bo[h*4+3]);
        __half2 h0 = __floats2half2_rn(r0, r1);
        __half2 h1 = __floats2half2_rn(r2, r3);
        o[h].x = *(uint32_t*)&h0; o[h].y = *(uint32_t*)&h1;
    }
    uint2* op = (uint2*)(out + (size_t)w*ldo) + lane*2;
    op[0] = o[0]; op[1] = o[1];
}

// ------------------------- classifier tail (warp per row) -------------------------
__global__ void k_cls(const float* __restrict__ Zin, const float* __restrict__ bc1,
                      const float* __restrict__ bng, const float* __restrict__ bnb,
                      const float* __restrict__ Wc2, const float* __restrict__ bc2,
                      float* __restrict__ out){
    int w = (blockIdx.x*blockDim.x + threadIdx.x) >> 5;
    if (w >= NN) return;
    int lane = threadIdx.x & 31;
    const float rs = rsqrtf(1.f + EPS);
    float o0 = 0.f, o1 = 0.f;
    #pragma unroll
    for (int i = 0; i < 4; i++){
        int c = lane + 32*i;
        float z = Zin[(size_t)w*128 + c] + bc1[c];
        z = fmaxf(z, 0.f);
        z = z * bng[c] * rs + bnb[c];
        o0 += z * Wc2[c*2 + 0];
        o1 += z * Wc2[c*2 + 1];
    }
    o0 = wred(o0); o1 = wred(o1);
    if (lane == 0){
        out[(size_t)w*2 + 0] = o0 + bc2[0];
        out[(size_t)w*2 + 1] = o1 + bc2[1];
    }
}

// ------------------------- launch -------------------------
template<typename T> static void* symaddr(T& sym){
    void* p = nullptr;
    cudaGetSymbolAddress(&p, sym);
    return p;
}

extern "C" void kernel_launch(void* const* d_in, const int* in_sizes, int n_in,
                              void* d_out, int out_size){
    const float* features = (const float*)d_in[0];
    const int*   edges    = (const int*)  d_in[1];
    const float* Wself1   = (const float*)d_in[2];
    const float* Wneigh1  = (const float*)d_in[3];
    const float* b1       = (const float*)d_in[4];
    const float* Wself2   = (const float*)d_in[5];
    const float* Wneigh2  = (const float*)d_in[6];
    const float* b2       = (const float*)d_in[7];
    const float* ln_g     = (const float*)d_in[8];
    const float* ln_b     = (const float*)d_in[9];
    const float* Wc1      = (const float*)d_in[10];
    const float* bc1      = (const float*)d_in[11];
    const float* bn_g     = (const float*)d_in[12];
    const float* bn_b     = (const float*)d_in[13];
    const float* Wc2      = (const float*)d_in[14];
    const float* bc2      = (const float*)d_in[15];
    float* out = (float*)d_out;

    __half* pA1  = (__half*)symaddr(g_A1);
    __half* pA2  = (__half*)symaddr(g_A2);
    float*  pACC = (float*) symaddr(g_ACC);
    __half* pH2  = (__half*)symaddr(g_H2);
    float*  pZ   = (float*) symaddr(g_Z);
    __half* pW1T = (__half*)symaddr(g_W1T);
    __half* pW2T = (__half*)symaddr(g_W2T);
    __half* pWcT = (__half*)symaddr(g_WcT);
    float*  pB1s = (float*) symaddr(g_b1s);
    float*  pB2s = (float*) symaddr(g_b2s);

    static int smem_set = 0;
    if (!smem_set){
        cudaFuncSetAttribute(k_hmma, cudaFuncAttributeMaxDynamicSharedMemorySize, GEMM_SMEM);
        smem_set = 1;
    }

    // --- CSR build ---
    k_zero_deg<<<(NROWS+255)/256, 256>>>();
    k_hist<<<(TOTE+255)/256, 256>>>(edges);
    k_scan1<<<SCAN_NB, 256>>>();
    k_scan2<<<1, 1024>>>();
    k_scan3<<<(NROWS+255)/256, 256>>>();
    k_fill<<<(TOTE+255)/256, 256>>>(edges);

    // --- weight prep ---
    k_w1<<<(256*1024)/256, 256>>>(Wself1, Wneigh1);
    k_w2<<<(256*2048)/256, 256>>>(Wself2, Wneigh2);
    k_wc<<<(128*256)/256, 256>>>(Wc1);
    k_bsum<<<1, 256>>>(b1, b2);

    const int MT = (NN + 127)/128;   // 782

    // --- layer 1 ---
    k_copyX<<<((size_t)NN*32 + 255)/256, 256>>>(features);
    k_mean_h<1><<<(NROWS*32 + 255)/256, 256>>>(pA1, 1024, pA1, 1024, 128);
    k_hmma<<<dim3(MT, 2), 256, GEMM_SMEM>>>(pA1, 1024, pW1T, 1024, pACC, 256, 1024, NN);
    k_ln<<<(NN*32 + 255)/256, 256>>>(pACC, pB1s, ln_g, ln_b, pA2, 2048);

    // --- layer 2 ---
    k_mean_h<2><<<(NROWS*32 + 255)/256, 256>>>(pA2, 2048, pA2, 2048, 256);
    k_hmma<<<dim3(MT, 2), 256, GEMM_SMEM>>>(pA2, 2048, pW2T, 2048, pACC, 256, 2048, NN);
    k_ln<<<(NN*32 + 255)/256, 256>>>(pACC, pB2s, ln_g + 256, ln_b + 256, pH2, 256);

    // --- classifier ---
    k_hmma<<<dim3(MT, 1), 256, GEMM_SMEM>>>(pH2, 256, pWcT, 256, pZ, 128, 256, NN);
    k_cls<<<(NN*32 + 255)/256, 256>>>(pZ, bc1, bn_g, bn_b, Wc2, bc2, out);
}

// round 6
// speedup vs baseline: 3.6738x; 1.1015x over previous
#include <cuda_runtime.h>
#include <cuda_fp16.h>
#include <cstdint>
#include <cstddef>

#define NN    100000
#define NR    7
#define NE    1600000
#define NROWS (NR*NN)
#define TOTE  (NR*NE)
#define SCAN_NB ((NROWS + 1023)/1024)
#define EPS   1e-5f

// ------------------------- scratch (static device memory) -------------------------
__device__ int   g_deg[NROWS];
__device__ int   g_ptr[NROWS];
__device__ int   g_cur[NROWS];
__device__ int   g_bs[SCAN_NB];
__device__ int   g_ssrc[TOTE];
__device__ __align__(128) __half g_A1[(size_t)(NN+128)*1024];   // [X | mean_0..6] fp16
__device__ __align__(128) __half g_A2[(size_t)(NN+128)*2048];   // [h1 | mean_0..6] fp16
__device__ __align__(128) float  g_ACC[(size_t)NN*256];         // GEMM out fp32
__device__ __align__(128) __half g_H2[(size_t)(NN+128)*256];    // layer2 LN out fp16
__device__ __align__(128) float  g_Z[(size_t)NN*128];           // classifier hidden fp32
__device__ __align__(128) __half g_W1T[256*1024];               // [N][K] fp16
__device__ __align__(128) __half g_W2T[256*2048];
__device__ __align__(128) __half g_WcT[128*256];
__device__ float g_b1s[256];
__device__ float g_b2s[256];

// ------------------------- helpers -------------------------
__device__ __forceinline__ float wred(float s){
    #pragma unroll
    for (int o = 16; o; o >>= 1) s += __shfl_xor_sync(0xffffffffu, s, o);
    return s;
}
__device__ __forceinline__ uint32_t smem_u32(const void* p){
    uint32_t a;
    asm("{ .reg .u64 t; cvta.to.shared.u64 t, %1; cvt.u32.u64 %0, t; }" : "=r"(a) : "l"(p));
    return a;
}
#define CP_ASYNC16(dst, src) \
    asm volatile("cp.async.cg.shared.global [%0], [%1], 16;" :: "r"(dst), "l"(src))
#define CP_COMMIT() asm volatile("cp.async.commit_group;" ::: "memory")
#define CP_WAIT1()  asm volatile("cp.async.wait_group 1;" ::: "memory")
#define CP_WAIT0()  asm volatile("cp.async.wait_group 0;" ::: "memory")

__device__ __forceinline__ void mma16816(float* c, const uint32_t* a, const uint32_t* b){
    asm volatile(
        "mma.sync.aligned.m16n8k16.row.col.f32.f16.f16.f32 "
        "{%0,%1,%2,%3}, {%4,%5,%6,%7}, {%8,%9}, {%0,%1,%2,%3};"
        : "+f"(c[0]), "+f"(c[1]), "+f"(c[2]), "+f"(c[3])
        : "r"(a[0]), "r"(a[1]), "r"(a[2]), "r"(a[3]), "r"(b[0]), "r"(b[1]));
}
// accumulate uint4 of 8 halves into 8 fp32
__device__ __forceinline__ void acc8(float* s, uint4 t){
    float2 f0 = __half22float2(*(__half2*)&t.x);
    float2 f1 = __half22float2(*(__half2*)&t.y);
    float2 f2 = __half22float2(*(__half2*)&t.z);
    float2 f3 = __half22float2(*(__half2*)&t.w);
    s[0]+=f0.x; s[1]+=f0.y; s[2]+=f1.x; s[3]+=f1.y;
    s[4]+=f2.x; s[5]+=f2.y; s[6]+=f3.x; s[7]+=f3.y;
}
__device__ __forceinline__ uint4 pack8(const float* s, float inv){
    __half2 h0 = __floats2half2_rn(s[0]*inv, s[1]*inv);
    __half2 h1 = __floats2half2_rn(s[2]*inv, s[3]*inv);
    __half2 h2 = __floats2half2_rn(s[4]*inv, s[5]*inv);
    __half2 h3 = __floats2half2_rn(s[6]*inv, s[7]*inv);
    uint4 o;
    o.x = *(uint32_t*)&h0; o.y = *(uint32_t*)&h1;
    o.z = *(uint32_t*)&h2; o.w = *(uint32_t*)&h3;
    return o;
}

// ------------------------- CSR build (4 edges / thread) -------------------------
__global__ void k_zero_deg(){
    int i = blockIdx.x*blockDim.x + threadIdx.x;
    if (i < NROWS/4) ((int4*)g_deg)[i] = make_int4(0,0,0,0);
    if (i == 0){ g_deg[NROWS-2] = 0; g_deg[NROWS-1] = 0; }  // NROWS=700000 %4==0 actually
}
__global__ void k_hist(const int* __restrict__ edges){
    int i4 = blockIdx.x*blockDim.x + threadIdx.x;
    if (i4 >= TOTE/4) return;
    int r = i4 / (NE/4), e4 = i4 - r*(NE/4);
    int4 d = ((const int4*)(edges + (size_t)r*2*NE + NE))[e4];
    int base = r*NN;
    atomicAdd(&g_deg[base + d.x], 1);
    atomicAdd(&g_deg[base + d.y], 1);
    atomicAdd(&g_deg[base + d.z], 1);
    atomicAdd(&g_deg[base + d.w], 1);
}
__global__ void k_scan1(){
    __shared__ int sh[256];
    int t = threadIdx.x;
    int base = blockIdx.x*1024 + t*4;
    int v[4];
    #pragma unroll
    for (int i = 0; i < 4; i++){
        int idx = base + i;
        v[i] = (idx < NROWS) ? g_deg[idx] : 0;
    }
    int tsum = v[0]+v[1]+v[2]+v[3];
    sh[t] = tsum; __syncthreads();
    for (int off = 1; off < 256; off <<= 1){
        int x = sh[t];
        int y = (t >= off) ? sh[t-off] : 0;
        __syncthreads();
        sh[t] = x + y;
        __syncthreads();
    }
    int excl = sh[t] - tsum;
    if (t == 255) g_bs[blockIdx.x] = sh[255];
    int run = excl;
    #pragma unroll
    for (int i = 0; i < 4; i++){
        int idx = base + i;
        if (idx < NROWS) g_ptr[idx] = run;
        run += v[i];
    }
}
__global__ void k_scan2(){
    __shared__ int sh[1024];
    int t = threadIdx.x;
    int v = (t < SCAN_NB) ? g_bs[t] : 0;
    sh[t] = v; __syncthreads();
    for (int off = 1; off < 1024; off <<= 1){
        int x = sh[t];
        int y = (t >= off) ? sh[t-off] : 0;
        __syncthreads();
        sh[t] = x + y;
        __syncthreads();
    }
    if (t < SCAN_NB) g_bs[t] = sh[t] - v;
}
__global__ void k_scan3(){
    int i = blockIdx.x*blockDim.x + threadIdx.x;
    if (i >= NROWS) return;
    int val = g_ptr[i] + g_bs[i >> 10];
    g_ptr[i] = val;
    g_cur[i] = val;
}
__global__ void k_fill(const int* __restrict__ edges){
    int i4 = blockIdx.x*blockDim.x + threadIdx.x;
    if (i4 >= TOTE/4) return;
    int r = i4 / (NE/4), e4 = i4 - r*(NE/4);
    const int* ebase = edges + (size_t)r*2*NE;
    int4 s = ((const int4*)ebase)[e4];
    int4 d = ((const int4*)(ebase + NE))[e4];
    int base = r*NN;
    g_ssrc[atomicAdd(&g_cur[base + d.x], 1)] = s.x;
    g_ssrc[atomicAdd(&g_cur[base + d.y], 1)] = s.y;
    g_ssrc[atomicAdd(&g_cur[base + d.z], 1)] = s.z;
    g_ssrc[atomicAdd(&g_cur[base + d.w], 1)] = s.w;
}

// ------------------------- feature staging (fp32 -> fp16 into A1) ---------------
__global__ void k_copyX(const float* __restrict__ X){
    size_t i = (size_t)blockIdx.x*blockDim.x + threadIdx.x;     // float4 units
    if (i >= (size_t)NN*32) return;
    size_t v = i >> 5, c4 = i & 31;
    float4 f = ((const float4*)X)[i];
    __half2 h0 = __floats2half2_rn(f.x, f.y);
    __half2 h1 = __floats2half2_rn(f.z, f.w);
    uint2 o; o.x = *(uint32_t*)&h0; o.y = *(uint32_t*)&h1;
    *((uint2*)(g_A1 + v*1024) + c4) = o;
}

// ------------------------- mean gather, layer 1 -------------------------
// half-warp (16 lanes) per (relation,node) row; uint4 (16B) per lane = 256B row.
__global__ void k_mean1(const __half* __restrict__ X,
                        __half* __restrict__ A){
    int ghw = (blockIdx.x*blockDim.x + threadIdx.x) >> 4;
    if (ghw >= NROWS) return;
    int lane = threadIdx.x & 15;
    int r = ghw / NN, v = ghw - r*NN;
    int beg = g_ptr[ghw], cnt = g_deg[ghw];
    float s[8] = {};
    const int* sp = g_ssrc + beg;
    int e = 0;
    for (; e + 2 <= cnt; e += 2){
        int s0 = __ldg(sp + e);
        int s1 = __ldg(sp + e + 1);
        uint4 t0 = __ldg((const uint4*)(X + (size_t)s0*1024) + lane);
        uint4 t1 = __ldg((const uint4*)(X + (size_t)s1*1024) + lane);
        acc8(s, t0);
        acc8(s, t1);
    }
    if (e < cnt){
        int s0 = __ldg(sp + e);
        uint4 t0 = __ldg((const uint4*)(X + (size_t)s0*1024) + lane);
        acc8(s, t0);
    }
    float inv = 1.f / fmaxf((float)cnt, 1.f);
    ((uint4*)(A + (size_t)v*1024 + 128*(1 + r)))[lane] = pack8(s, inv);
}

// ------------------------- mean gather, layer 2 -------------------------
// full warp per row; uint4 (16B) per lane = 512B row (256 halves).
__global__ void k_mean2(const __half* __restrict__ X,
                        __half* __restrict__ A){
    int gw = (blockIdx.x*blockDim.x + threadIdx.x) >> 5;
    if (gw >= NROWS) return;
    int lane = threadIdx.x & 31;
    int r = gw / NN, v = gw - r*NN;
    int beg = g_ptr[gw], cnt = g_deg[gw];
    float s[8] = {};
    const int* sp = g_ssrc + beg;
    int e = 0;
    for (; e + 2 <= cnt; e += 2){
        int s0 = __ldg(sp + e);
        int s1 = __ldg(sp + e + 1);
        uint4 t0 = __ldg((const uint4*)(X + (size_t)s0*2048) + lane);
        uint4 t1 = __ldg((const uint4*)(X + (size_t)s1*2048) + lane);
        acc8(s, t0);
        acc8(s, t1);
    }
    if (e < cnt){
        int s0 = __ldg(sp + e);
        uint4 t0 = __ldg((const uint4*)(X + (size_t)s0*2048) + lane);
        acc8(s, t0);
    }
    float inv = 1.f / fmaxf((float)cnt, 1.f);
    ((uint4*)(A + (size_t)v*2048 + 256*(1 + r)))[lane] = pack8(s, inv);
}

// ------------------------- weight prep ([N][K] fp16) -------------------------
__global__ void k_w1(const float* __restrict__ Ws, const float* __restrict__ Wn){
    int i = blockIdx.x*blockDim.x + threadIdx.x;
    if (i >= 256*1024) return;
    int n = i >> 10, k = i & 1023;
    float val;
    if (k < 128){
        val = 0.f;
        #pragma unroll
        for (int r = 0; r < NR; r++) val += Ws[((size_t)r*128 + k)*256 + n];
    } else {
        int r = (k >> 7) - 1, kk = k & 127;
        val = Wn[((size_t)r*128 + kk)*256 + n];
    }
    g_W1T[i] = __float2half(val);
}
__global__ void k_w2(const float* __restrict__ Ws, const float* __restrict__ Wn){
    int i = blockIdx.x*blockDim.x + threadIdx.x;
    if (i >= 256*2048) return;
    int n = i >> 11, k = i & 2047;
    float val;
    if (k < 256){
        val = 0.f;
        #pragma unroll
        for (int r = 0; r < NR; r++) val += Ws[((size_t)r*256 + k)*256 + n];
    } else {
        int r = (k >> 8) - 1, kk = k & 255;
        val = Wn[((size_t)r*256 + kk)*256 + n];
    }
    g_W2T[i] = __float2half(val);
}
__global__ void k_wc(const float* __restrict__ Wc1){
    int i = blockIdx.x*blockDim.x + threadIdx.x;
    if (i >= 128*256) return;
    int n = i >> 8, k = i & 255;
    g_WcT[i] = __float2half(Wc1[(size_t)k*128 + n]);
}
__global__ void k_bsum(const float* __restrict__ b1, const float* __restrict__ b2){
    int c = threadIdx.x;
    float s1 = 0.f, s2 = 0.f;
    #pragma unroll
    for (int r = 0; r < NR; r++){ s1 += b1[r*256 + c]; s2 += b2[r*256 + c]; }
    g_b1s[c] = s1 * (1.f/7.f);
    g_b2s[c] = s2 * (1.f/7.f);
}

// ------------------------- fp16 tensor-core GEMM -------------------------
#define STRH 40
#define TILE_H (128*STRH)
#define GEMM_SMEM (4*TILE_H*2)

__global__ void __launch_bounds__(256, 2) k_hmma(
    const __half* __restrict__ A, int lda,
    const __half* __restrict__ BT, int ldb,
    float* __restrict__ C, int ldc,
    int K, int M)
{
    extern __shared__ __half sm[];
    __half* Ab[2] = { sm,            sm + TILE_H };
    __half* Bb[2] = { sm + 2*TILE_H, sm + 3*TILE_H };

    int tid = threadIdx.x, wid = tid >> 5, lane = tid & 31;
    int warpRow = (wid >> 2) * 64;
    int warpCol = (wid & 3) * 32;
    int rowBase = blockIdx.x * 128;
    int colBase = blockIdx.y * 128;

    uint32_t sA[2], sB[2];
    sA[0] = smem_u32(Ab[0]); sA[1] = smem_u32(Ab[1]);
    sB[0] = smem_u32(Bb[0]); sB[1] = smem_u32(Bb[1]);

    float acc[4][4][4] = {};
    const int nT = K >> 5;

    auto load_tile = [&](int t, int buf){
        int k0 = t << 5;
        #pragma unroll
        for (int i = 0; i < 2; i++){
            int idx = i*256 + tid;
            int row = idx >> 2, ch = idx & 3;
            const __half* srcA = A + (size_t)(rowBase + row)*lda + k0 + ch*8;
            CP_ASYNC16(sA[buf] + (row*STRH + ch*8)*2, srcA);
            const __half* srcB = BT + (size_t)(colBase + row)*ldb + k0 + ch*8;
            CP_ASYNC16(sB[buf] + (row*STRH + ch*8)*2, srcB);
        }
        CP_COMMIT();
    };

    load_tile(0, 0);

    for (int t = 0; t < nT; t++){
        int buf = t & 1;
        if (t + 1 < nT){ load_tile(t+1, buf^1); CP_WAIT1(); }
        else           { CP_WAIT0(); }
        __syncthreads();

        const __half* As = Ab[buf];
        const __half* Bs = Bb[buf];
        #pragma unroll
        for (int kk = 0; kk < 2; kk++){
            uint32_t a[4][4], b[4][2];
            int ar = warpRow + (lane >> 2);
            int c0 = kk*16 + (lane & 3)*2;
            #pragma unroll
            for (int mt = 0; mt < 4; mt++){
                const __half* ap = As + (ar + mt*16)*STRH + c0;
                a[mt][0] = *(const uint32_t*)(ap);
                a[mt][1] = *(const uint32_t*)(ap + 8*STRH);
                a[mt][2] = *(const uint32_t*)(ap + 8);
                a[mt][3] = *(const uint32_t*)(ap + 8*STRH + 8);
            }
            int bn = warpCol + (lane >> 2);
            #pragma unroll
            for (int nt = 0; nt < 4; nt++){
                const __half* bp = Bs + (bn + nt*8)*STRH + c0;
                b[nt][0] = *(const uint32_t*)(bp);
                b[nt][1] = *(const uint32_t*)(bp + 8);
            }
            #pragma unroll
            for (int mt = 0; mt < 4; mt++)
                #pragma unroll
                for (int nt = 0; nt < 4; nt++)
                    mma16816(acc[mt][nt], a[mt], b[nt]);
        }
        __syncthreads();
    }

    #pragma unroll
    for (int mt = 0; mt < 4; mt++){
        int r0 = rowBase + warpRow + mt*16 + (lane >> 2);
        int r1 = r0 + 8;
        #pragma unroll
        for (int nt = 0; nt < 4; nt++){
            int c0 = colBase + warpCol + nt*8 + (lane & 3)*2;
            if (r0 < M) *(float2*)(C + (size_t)r0*ldc + c0) = make_float2(acc[mt][nt][0], acc[mt][nt][1]);
            if (r1 < M) *(float2*)(C + (size_t)r1*ldc + c0) = make_float2(acc[mt][nt][2], acc[mt][nt][3]);
        }
    }
}

// ------------------------- LayerNorm + ReLU (warp per row, fp16 out) -----------
__global__ void k_ln(const float* __restrict__ ACC, const float* __restrict__ bsum,
                     const float* __restrict__ g, const float* __restrict__ b,
                     __half* __restrict__ out, int ldo){
    int w = (blockIdx.x*blockDim.x + threadIdx.x) >> 5;
    if (w >= NN) return;
    int lane = threadIdx.x & 31;
    const float4* ap = (const float4*)(ACC + (size_t)w*256) + lane*2;
    const float4* bp = (const float4*)bsum + lane*2;
    float4 v0 = ap[0], v1 = ap[1];
    float4 s0 = bp[0], s1 = bp[1];
    float y[8];
    y[0] = v0.x*(1.f/7.f) + s0.x; y[1] = v0.y*(1.f/7.f) + s0.y;
    y[2] = v0.z*(1.f/7.f) + s0.z; y[3] = v0.w*(1.f/7.f) + s0.w;
    y[4] = v1.x*(1.f/7.f) + s1.x; y[5] = v1.y*(1.f/7.f) + s1.y;
    y[6] = v1.z*(1.f/7.f) + s1.z; y[7] = v1.w*(1.f/7.f) + s1.w;
    float s = 0.f;
    #pragma unroll
    for (int i = 0; i < 8; i++) s += y[i];
    float mu = wred(s) * (1.f/256.f);
    float vs = 0.f;
    #pragma unroll
    for (int i = 0; i < 8; i++){ float d = y[i]-mu; vs += d*d; }
    float var = wred(vs) * (1.f/256.f);
    float rstd = rsqrtf(var + EPS);
    const float4* gp = (const float4*)g + lane*2;
    const float4* bbp = (const float4*)b + lane*2;
    float4 g0 = gp[0], g1 = gp[1];
    float4 b0 = bbp[0], b1 = bbp[1];
    float go[8] = {g0.x,g0.y,g0.z,g0.w,g1.x,g1.y,g1.z,g1.w};
    float bo[8] = {b0.x,b0.y,b0.z,b0.w,b1.x,b1.y,b1.z,b1.w};
    uint2 o[2];
    #pragma unroll
    for (int h = 0; h < 2; h++){
        float r0 = fmaxf(0.f, (y[h*4+0]-mu)*rstd*go[h*4+0] + bo[h*4+0]);
        float r1 = fmaxf(0.f, (y[h*4+1]-mu)*rstd*go[h*4+1] + bo[h*4+1]);
        float r2 = fmaxf(0.f, (y[h*4+2]-mu)*rstd*go[h*4+2] + bo[h*4+2]);
        float r3 = fmaxf(0.f, (y[h*4+3]-mu)*rstd*go[h*4+3] + bo[h*4+3]);
        __half2 h0 = __floats2half2_rn(r0, r1);
        __half2 h1 = __floats2half2_rn(r2, r3);
        o[h].x = *(uint32_t*)&h0; o[h].y = *(uint32_t*)&h1;
    }
    uint2* op = (uint2*)(out + (size_t)w*ldo) + lane*2;
    op[0] = o[0]; op[1] = o[1];
}

// ------------------------- classifier tail (warp per row) -------------------------
__global__ void k_cls(const float* __restrict__ Zin, const float* __restrict__ bc1,
                      const float* __restrict__ bng, const float* __restrict__ bnb,
                      const float* __restrict__ Wc2, const float* __restrict__ bc2,
                      float* __restrict__ out){
    int w = (blockIdx.x*blockDim.x + threadIdx.x) >> 5;
    if (w >= NN) return;
    int lane = threadIdx.x & 31;
    const float rs = rsqrtf(1.f + EPS);
    float o0 = 0.f, o1 = 0.f;
    #pragma unroll
    for (int i = 0; i < 4; i++){
        int c = lane + 32*i;
        float z = Zin[(size_t)w*128 + c] + bc1[c];
        z = fmaxf(z, 0.f);
        z = z * bng[c] * rs + bnb[c];
        o0 += z * Wc2[c*2 + 0];
        o1 += z * Wc2[c*2 + 1];
    }
    o0 = wred(o0); o1 = wred(o1);
    if (lane == 0){
        out[(size_t)w*2 + 0] = o0 + bc2[0];
        out[(size_t)w*2 + 1] = o1 + bc2[1];
    }
}

// ------------------------- launch -------------------------
template<typename T> static void* symaddr(T& sym){
    void* p = nullptr;
    cudaGetSymbolAddress(&p, sym);
    return p;
}

extern "C" void kernel_launch(void* const* d_in, const int* in_sizes, int n_in,
                              void* d_out, int out_size){
    const float* features = (const float*)d_in[0];
    const int*   edges    = (const int*)  d_in[1];
    const float* Wself1   = (const float*)d_in[2];
    const float* Wneigh1  = (const float*)d_in[3];
    const float* b1       = (const float*)d_in[4];
    const float* Wself2   = (const float*)d_in[5];
    const float* Wneigh2  = (const float*)d_in[6];
    const float* b2       = (const float*)d_in[7];
    const float* ln_g     = (const float*)d_in[8];
    const float* ln_b     = (const float*)d_in[9];
    const float* Wc1      = (const float*)d_in[10];
    const float* bc1      = (const float*)d_in[11];
    const float* bn_g     = (const float*)d_in[12];
    const float* bn_b     = (const float*)d_in[13];
    const float* Wc2      = (const float*)d_in[14];
    const float* bc2      = (const float*)d_in[15];
    float* out = (float*)d_out;

    __half* pA1  = (__half*)symaddr(g_A1);
    __half* pA2  = (__half*)symaddr(g_A2);
    float*  pACC = (float*) symaddr(g_ACC);
    __half* pH2  = (__half*)symaddr(g_H2);
    float*  pZ   = (float*) symaddr(g_Z);
    __half* pW1T = (__half*)symaddr(g_W1T);
    __half* pW2T = (__half*)symaddr(g_W2T);
    __half* pWcT = (__half*)symaddr(g_WcT);
    float*  pB1s = (float*) symaddr(g_b1s);
    float*  pB2s = (float*) symaddr(g_b2s);

    static int smem_set = 0;
    if (!smem_set){
        cudaFuncSetAttribute(k_hmma, cudaFuncAttributeMaxDynamicSharedMemorySize, GEMM_SMEM);
        smem_set = 1;
    }

    // --- CSR build ---
    k_zero_deg<<<(NROWS/4+255)/256, 256>>>();
    k_hist<<<(TOTE/4+255)/256, 256>>>(edges);
    k_scan1<<<SCAN_NB, 256>>>();
    k_scan2<<<1, 1024>>>();
    k_scan3<<<(NROWS+255)/256, 256>>>();
    k_fill<<<(TOTE/4+255)/256, 256>>>(edges);

    // --- weight prep ---
    k_w1<<<(256*1024)/256, 256>>>(Wself1, Wneigh1);
    k_w2<<<(256*2048)/256, 256>>>(Wself2, Wneigh2);
    k_wc<<<(128*256)/256, 256>>>(Wc1);
    k_bsum<<<1, 256>>>(b1, b2);

    const int MT = (NN + 127)/128;   // 782

    // --- layer 1 ---
    k_copyX<<<((size_t)NN*32 + 255)/256, 256>>>(features);
    k_mean1<<<(NROWS*16 + 255)/256, 256>>>(pA1, pA1);
    k_hmma<<<dim3(MT, 2), 256, GEMM_SMEM>>>(pA1, 1024, pW1T, 1024, pACC, 256, 1024, NN);
    k_ln<<<(NN*32 + 255)/256, 256>>>(pACC, pB1s, ln_g, ln_b, pA2, 2048);

    // --- layer 2 ---
    k_mean2<<<(NROWS*32 + 255)/256, 256>>>(pA2, pA2);
    k_hmma<<<dim3(MT, 2), 256, GEMM_SMEM>>>(pA2, 2048, pW2T, 2048, pACC, 256, 2048, NN);
    k_ln<<<(NN*32 + 255)/256, 256>>>(pACC, pB2s, ln_g + 256, ln_b + 256, pH2, 256);

    // --- classifier ---
    k_hmma<<<dim3(MT, 1), 256, GEMM_SMEM>>>(pH2, 256, pWcT, 256, pZ, 128, 256, NN);
    k_cls<<<(NN*32 + 255)/256, 256>>>(pZ, bc1, bn_g, bn_b, Wc2, bc2, out);
}